// round 10
// baseline (speedup 1.0000x reference)
#include <cuda_runtime.h>
#include <math.h>

#define Bt    16
#define St    128
#define Nn    2048
#define Ee    2032
#define Hh    256
#define DEc   192
#define DRc   64
#define Lc    12
#define NTH   512
#define CSZ   8

typedef unsigned long long u64;

// ---------------- device scratch (no dynamic allocation allowed) ------------
__device__ float g_ix[Nn * Hh];
__device__ float g_fx[Nn * Hh];
__device__ float g_ox[Nn * Hh];
__device__ float g_ux[Nn * Hh];
__device__ float g_h [Nn * Hh];
__device__ float g_pool[Bt * 8 * Hh];
__device__ int   g_child_start[Nn + 1];
__device__ int   g_child_list [Ee];
__device__ int   g_tlist[Nn];        // per-tree level-ordered node ids

// ---------------- helpers ----------------------------------------------------
__device__ __forceinline__ u64 dup2(float a) {
    u64 r; asm("mov.b64 %0,{%1,%1};" : "=l"(r) : "f"(a)); return r;
}
__device__ __forceinline__ void fma2(u64& d, u64 a, u64 b) {
    asm("fma.rn.f32x2 %0,%1,%2,%0;" : "+l"(d) : "l"(a), "l"(b));
}
__device__ __forceinline__ float red2(u64 v) {
    float a, b; asm("mov.b64 {%0,%1},%2;" : "=f"(a), "=f"(b) : "l"(v));
    return a + b;
}
__device__ __forceinline__ float lo2(u64 v) {
    float a, b; asm("mov.b64 {%0,%1},%2;" : "=f"(a), "=f"(b) : "l"(v)); return a;
}
__device__ __forceinline__ float hi2(u64 v) {
    float a, b; asm("mov.b64 {%0,%1},%2;" : "=f"(a), "=f"(b) : "l"(v)); return b;
}
__device__ __forceinline__ float sigm(float x) { return 1.f / (1.f + __expf(-x)); }

// poll own-SMEM done counter (generic addr) with cluster-scope acquire
__device__ __forceinline__ void waitdone8(const int* p) {
    int it = 0;
    for (;;) {
        int v;
        asm volatile("ld.acquire.cluster.b32 %0,[%1];" : "=r"(v) : "l"(p) : "memory");
        if (v == CSZ) break;
        if (++it > 64) __nanosleep(64);
    }
}
// increment done[s] in ALL cluster CTAs (release: orders prior st.global/st.shared)
__device__ __forceinline__ void rel_all(unsigned laddr) {
#pragma unroll
    for (int r = 0; r < CSZ; r++) {
        asm volatile(
            "{ .reg .b32 ra;\n"
            "  mapa.shared::cluster.u32 ra, %0, %1;\n"
            "  red.release.cluster.shared::cluster.add.u32 [ra], 1;\n}"
            :: "r"(laddr), "r"(r) : "memory");
    }
}

// ---------------- preprocess: child CSR + per-tree level lists --------------
__global__ void __launch_bounds__(512) preprocess_kernel(
    const int* __restrict__ child_idx,
    const int* __restrict__ parent_idx,
    const int* __restrict__ node_height)
{
    __shared__ int s_cnt[Nn];
    __shared__ int s_aux[512];
    __shared__ int s_par[Ee];
    __shared__ int s_tl[Bt * 24];     // per-(tree,level) cursors
    const int t = threadIdx.x;

    for (int i = t; i < Nn; i += 512) s_cnt[i] = 0;
    for (int e = t; e < Ee; e += 512) s_par[e] = parent_idx[e];
    for (int i = t; i < Bt * 24; i += 512) s_tl[i] = 0;
    __syncthreads();

    for (int e = t; e < Ee; e += 512) atomicAdd(&s_cnt[s_par[e]], 1);
    for (int i = t; i < Nn; i += 512)
        atomicAdd(&s_tl[(i >> 7) * 24 + node_height[i]], 1);
    __syncthreads();

    // exclusive scan of 2048 child counts
    int v[4]; int s = 0;
#pragma unroll
    for (int r = 0; r < 4; r++) { v[r] = s_cnt[t * 4 + r]; s += v[r]; }
    s_aux[t] = s;
    __syncthreads();
    for (int off = 1; off < 512; off <<= 1) {
        int x = (t >= off) ? s_aux[t - off] : 0;
        __syncthreads();
        s_aux[t] += x;
        __syncthreads();
    }
    int run = (t == 0) ? 0 : s_aux[t - 1];
#pragma unroll
    for (int r = 0; r < 4; r++) {
        int c = v[r];
        g_child_start[t * 4 + r] = run;
        s_cnt[t * 4 + r] = run;
        run += c;
    }
    if (t == 511) g_child_start[Nn] = run;
    __syncthreads();

    // per-tree level prefix (counts -> scatter cursors)
    if (t < Bt) {
        int acc = 0;
        for (int l = 0; l < 22; l++) {
            int c = s_tl[t * 24 + l];
            s_tl[t * 24 + l] = acc;
            acc += c;
        }
    }
    __syncthreads();

    // warp-per-tree child scatter: rank = #earlier same-parent edges in tree
    {
        int w = t >> 5, lane = t & 31;
        if (w < Bt) {
            int e0 = w * (St - 1);
            for (int el = lane; el < St - 1; el += 32) {
                int e = e0 + el;
                int p = s_par[e];
                int rank = 0;
                for (int e2 = e0; e2 < e; ++e2) rank += (s_par[e2] == p) ? 1 : 0;
                g_child_list[s_cnt[p] + rank] = child_idx[e];
            }
        }
    }
    // per-tree level-ordered node scatter
    for (int i = t; i < Nn; i += 512) {
        int b = i >> 7;
        int pos = atomicAdd(&s_tl[b * 24 + node_height[i]], 1);
        g_tlist[b * St + pos] = i;
    }
}

// ---------------- fused embed + input GEMMs: x[2048,256] @ W[256,256] -------
__global__ void __launch_bounds__(256) input_gemm_kernel(
    const int* __restrict__ xs, const int* __restrict__ rels,
    const float* __restrict__ embW, const float* __restrict__ relW,
    const float* __restrict__ Wix, const float* __restrict__ Wfx,
    const float* __restrict__ Wox, const float* __restrict__ Wux,
    const float* __restrict__ bix, const float* __restrict__ bfx,
    int zbase)
{
    __shared__ __align__(16) float As[16][68];
    __shared__ __align__(16) float Bs[16][68];
    __shared__ int s_xs[64], s_rels[64];
    const int mz = blockIdx.z + zbase;
    const float* W  = (mz == 0) ? Wix : (mz == 1) ? Wfx : (mz == 2) ? Wox : Wux;
    const float* bp = (mz == 0) ? bix : (mz == 1) ? bfx : nullptr;
    float* O = (mz == 0) ? g_ix : (mz == 1) ? g_fx : (mz == 2) ? g_ox : g_ux;

    const int t = threadIdx.x;
    const int tx = t & 15, ty = t >> 4;
    const int row0 = blockIdx.y * 64, col0 = blockIdx.x * 64;
    if (t < 64) { s_xs[t] = xs[row0 + t]; s_rels[t] = rels[row0 + t]; }
    __syncthreads();

    u64 acc[4][2] = {};

    for (int kk = 0; kk < 256; kk += 16) {
        {
            int m = t >> 2, kq = (t & 3) * 4;
            int gk = kk + kq;
            float4 a;
            if (gk < DEc) a = *(const float4*)(embW + (size_t)s_xs[m] * DEc + gk);
            else          a = *(const float4*)(relW + (size_t)s_rels[m] * DRc + (gk - DEc));
            As[kq + 0][m] = a.x; As[kq + 1][m] = a.y;
            As[kq + 2][m] = a.z; As[kq + 3][m] = a.w;
            int k = t >> 4, nq = (t & 15) * 4;
            float4 b = *(const float4*)(W + (kk + k) * 256 + col0 + nq);
            *(float4*)&Bs[k][nq] = b;
        }
        __syncthreads();
#pragma unroll
        for (int k = 0; k < 16; k++) {
            float4 a = *(const float4*)&As[k][ty * 4];
            u64 b0 = *(const u64*)&Bs[k][tx * 4];
            u64 b1 = *(const u64*)&Bs[k][tx * 4 + 2];
            u64 d;
            d = dup2(a.x); fma2(acc[0][0], d, b0); fma2(acc[0][1], d, b1);
            d = dup2(a.y); fma2(acc[1][0], d, b0); fma2(acc[1][1], d, b1);
            d = dup2(a.z); fma2(acc[2][0], d, b0); fma2(acc[2][1], d, b1);
            d = dup2(a.w); fma2(acc[3][0], d, b0); fma2(acc[3][1], d, b1);
        }
        __syncthreads();
    }
    int cc0 = col0 + tx * 4;
    float4 bb = make_float4(0.f, 0.f, 0.f, 0.f);
    if (bp) bb = *(const float4*)(bp + cc0);
#pragma unroll
    for (int r = 0; r < 4; r++) {
        int row = row0 + ty * 4 + r;
        float4 o;
        o.x = lo2(acc[r][0]) + bb.x; o.y = hi2(acc[r][0]) + bb.y;
        o.z = lo2(acc[r][1]) + bb.z; o.w = hi2(acc[r][1]) + bb.w;
        *(float4*)(O + row * 256 + cc0) = o;
    }
}

// ---------------- tree-per-cluster dataflow recurrence ----------------------
// Cluster of 8 CTAs per tree; CTA rank = 32-col slice. Per-node done counters
// in each CTA's SMEM, incremented via DSMEM red.release from all 8 producers.
__global__ void __launch_bounds__(NTH) __cluster_dims__(CSZ, 1, 1)
rec_kernel(
    const float* __restrict__ Wih, const float* __restrict__ Woh,
    const float* __restrict__ Wuh, const float* __restrict__ Wfh,
    const float* __restrict__ bih_g, const float* __restrict__ bfh_g)
{
    extern __shared__ __align__(16) float sm[];
    float* Wi = sm;              // each 8192 floats, pair-interleaved over k:
    float* Wo = sm + 8192;       //   W*[k2*64 + lane*2 + s] = W[2*k2+s][cb*32+lane]
    float* Wu = sm + 16384;
    float* Wf = sm + 24576;
    float* hchAll = sm + 32768;           // 16 warps x 256
    float* c_loc  = sm + 32768 + 4096;    // 128 nodes x 32 cols
    int*   done   = (int*)(sm + 32768 + 8192);   // 128 counters
    int*   s_cur  = done + St;

    const int t = threadIdx.x;
    const int lane = t & 31, w = t >> 5;
    const int tree = blockIdx.x >> 3;
    const int cb   = blockIdx.x & 7;
    const int col = cb * 32 + lane;

    for (int p = t; p < 4096; p += NTH) {
        int k2 = p >> 5, j = p & 31;
        int g0 = (2 * k2) * 256 + cb * 32 + j;
        int o = k2 * 64 + j * 2;
        Wi[o] = Wih[g0]; Wi[o + 1] = Wih[g0 + 256];
        Wo[o] = Woh[g0]; Wo[o + 1] = Woh[g0 + 256];
        Wu[o] = Wuh[g0]; Wu[o + 1] = Wuh[g0 + 256];
        Wf[o] = Wfh[g0]; Wf[o + 1] = Wfh[g0 + 256];
    }
    if (t < St) done[t] = 0;
    if (t == 0) *s_cur = 0;
    const float bih = bih_g[col];
    const float bfh = bfh_g[col];
    float* hch = hchAll + w * 256;
    const u64* Wi2 = (const u64*)Wi;
    const u64* Wo2 = (const u64*)Wo;
    const u64* Wu2 = (const u64*)Wu;
    const u64* Wf2 = (const u64*)Wf;
    const unsigned done_sh = (unsigned)__cvta_generic_to_shared(done);
    __syncthreads();
    // all cluster CTAs' done[] must be zeroed before any remote red arrives
    asm volatile("barrier.cluster.arrive.aligned;" ::: "memory");
    asm volatile("barrier.cluster.wait.aligned;" ::: "memory");

    const int* tl = g_tlist + tree * St;

    for (;;) {
        int pos;
        if (lane == 0) pos = atomicAdd(s_cur, 1);
        pos = __shfl_sync(0xffffffffu, pos, 0);
        if (pos >= St) break;
        int n = tl[pos];
        int sn = n & 127;
        int cs0 = g_child_start[n], cs1 = g_child_start[n + 1];
        float ixv = g_ix[n * 256 + col];
        float oxv = g_ox[n * 256 + col];
        float uxv = g_ux[n * 256 + col];
        float ov, cn;
        if (cs1 == cs0) {                          // leaf: h_sum = 0, fc = 0
            float iv = sigm(ixv + bih);
            ov = sigm(oxv);
            cn = iv * tanhf(uxv);
        } else {
            float fxn = g_fx[n * 256 + col];
            float rs[8];
#pragma unroll
            for (int q = 0; q < 8; q++) rs[q] = 0.f;
            float fc = 0.f;

            for (int e = cs0; e < cs1; e++) {
                int ch = g_child_list[e];
                int sch = ch & 127;
                waitdone8(done + sch);
                const float* hr = g_h + ch * 256;
#pragma unroll
                for (int q = 0; q < 8; q++) {
                    float vv = __ldcg(hr + q * 32 + lane);
                    hch[q * 32 + lane] = vv;
                    rs[q] += vv;
                }
                float cch = c_loc[sch * 32 + lane];
                __syncwarp();
                u64 a0 = 0, a1 = 0, a2 = 0, a3 = 0;
#pragma unroll 8
                for (int k2 = 0; k2 < 128; k2 += 4) {
                    fma2(a0, *(const u64*)(hch + 2 * k2),     Wf2[(k2 + 0) * 32 + lane]);
                    fma2(a1, *(const u64*)(hch + 2 * k2 + 2), Wf2[(k2 + 1) * 32 + lane]);
                    fma2(a2, *(const u64*)(hch + 2 * k2 + 4), Wf2[(k2 + 2) * 32 + lane]);
                    fma2(a3, *(const u64*)(hch + 2 * k2 + 6), Wf2[(k2 + 3) * 32 + lane]);
                }
                float fd = red2(a0) + red2(a1) + red2(a2) + red2(a3);
                float f = sigm(fd + bfh + fxn);
                fc = fmaf(f, cch, fc);
                __syncwarp();
            }

            // h_sum -> smem (broadcast source for i/o/u dots)
#pragma unroll
            for (int q = 0; q < 8; q++) hch[q * 32 + lane] = rs[q];
            __syncwarp();
            u64 i0 = 0, i1 = 0, o0 = 0, o1 = 0, u0 = 0, u1 = 0;
#pragma unroll 4
            for (int k2 = 0; k2 < 128; k2 += 2) {
                u64 p01 = *(const u64*)(hch + 2 * k2);
                u64 p23 = *(const u64*)(hch + 2 * k2 + 2);
                fma2(i0, p01, Wi2[(k2 + 0) * 32 + lane]);
                fma2(i1, p23, Wi2[(k2 + 1) * 32 + lane]);
                fma2(o0, p01, Wo2[(k2 + 0) * 32 + lane]);
                fma2(o1, p23, Wo2[(k2 + 1) * 32 + lane]);
                fma2(u0, p01, Wu2[(k2 + 0) * 32 + lane]);
                fma2(u1, p23, Wu2[(k2 + 1) * 32 + lane]);
            }
            float iv = sigm(ixv + red2(i0) + red2(i1) + bih);
            ov = sigm(oxv + red2(o0) + red2(o1));
            float uv = tanhf(uxv + red2(u0) + red2(u1));
            cn = fmaf(iv, uv, fc);
            __syncwarp();
        }
        c_loc[sn * 32 + lane] = cn;
        __stcg(g_h + n * 256 + col, ov * tanhf(cn));
        __syncwarp();
        if (lane == 0) rel_all(done_sh + (unsigned)(sn * 4));
    }

    // no CTA may exit while peers' DSMEM reds targeting it are in flight
    asm volatile("barrier.cluster.arrive.aligned;" ::: "memory");
    asm volatile("barrier.cluster.wait.aligned;" ::: "memory");
}

// ---------------- parallel 2-stage max-pool + output ------------------------
__global__ void __launch_bounds__(256) pool1_kernel()
{
    int b = blockIdx.x, chn = blockIdx.y, t = threadIdx.x;
    const float* hb = g_h + ((size_t)b * St + chn * 16) * Hh;
    float m = -1e30f;
#pragma unroll
    for (int s2 = 0; s2 < 16; s2++) m = fmaxf(m, hb[s2 * Hh + t]);
    g_pool[(b * 8 + chn) * Hh + t] = m;
}

__global__ void __launch_bounds__(256) pool2_kernel(
    const float* __restrict__ Wout, const float* __restrict__ bout,
    float* __restrict__ out)
{
    __shared__ float pooled[Hh];
    int b = blockIdx.x, t = threadIdx.x;
    float m = -1e30f;
#pragma unroll
    for (int chn = 0; chn < 8; chn++)
        m = fmaxf(m, g_pool[(b * 8 + chn) * Hh + t]);
    pooled[t] = m;
    __syncthreads();
    if (t < Lc) {
        float acc = bout[t];
        for (int k = 0; k < Hh; k++) acc = fmaf(pooled[k], Wout[k * Lc + t], acc);
        out[b * Lc + t] = acc;
    }
}

// ---------------- host-side launch ------------------------------------------
extern "C" void kernel_launch(void* const* d_in, const int* in_sizes, int n_in,
                              void* d_out, int out_size)
{
    int off = (in_sizes[5] == 1) ? 6 : 5;

    const int* xs        = (const int*)d_in[0];
    const int* rels      = (const int*)d_in[1];
    const int* child_idx = (const int*)d_in[2];
    const int* parent_idx= (const int*)d_in[3];
    const int* height    = (const int*)d_in[4];
    const float* embW  = (const float*)d_in[off + 0];
    const float* relW  = (const float*)d_in[off + 1];
    const float* W_ix  = (const float*)d_in[off + 2];
    const float* b_ix  = (const float*)d_in[off + 3];
    const float* W_ih  = (const float*)d_in[off + 4];
    const float* b_ih  = (const float*)d_in[off + 5];
    const float* W_fx  = (const float*)d_in[off + 6];
    const float* b_fx  = (const float*)d_in[off + 7];
    const float* W_fh  = (const float*)d_in[off + 8];
    const float* b_fh  = (const float*)d_in[off + 9];
    const float* W_ox  = (const float*)d_in[off + 10];
    const float* W_oh  = (const float*)d_in[off + 11];
    const float* W_ux  = (const float*)d_in[off + 12];
    const float* W_uh  = (const float*)d_in[off + 13];
    const float* W_out = (const float*)d_in[off + 14];
    const float* b_out = (const float*)d_in[off + 15];

    // W 128KB + hch 16KB + c_loc 16KB + done/cursor
    const int REC_SMEM = 32768 * 4 + 8192 * 4 + (St + 16) * 4;
    cudaFuncSetAttribute(rec_kernel,
                         cudaFuncAttributeMaxDynamicSharedMemorySize, REC_SMEM);

    preprocess_kernel<<<1, 512>>>(child_idx, parent_idx, height);
    dim3 gg(4, 32, 2);
    input_gemm_kernel<<<gg, 256>>>(xs, rels, embW, relW,
                                   W_ix, W_fx, W_ox, W_ux, b_ix, b_fx, 0);
    input_gemm_kernel<<<gg, 256>>>(xs, rels, embW, relW,
                                   W_ix, W_fx, W_ox, W_ux, b_ix, b_fx, 2);
    rec_kernel<<<Bt * CSZ, NTH, REC_SMEM>>>(W_ih, W_oh, W_uh, W_fh, b_ih, b_fh);
    pool1_kernel<<<dim3(16, 8), 256>>>();
    pool2_kernel<<<Bt, 256>>>(W_out, b_out, (float*)d_out);
}

// round 12
// speedup vs baseline: 1.0632x; 1.0632x over previous
#include <cuda_runtime.h>
#include <math.h>

#define Bt    16
#define St    128
#define Nn    2048
#define Ee    2032
#define Hh    256
#define DEc   192
#define DRc   64
#define Lc    12
#define NLEVc 21
#define NCTA  144
#define NTH   512

typedef unsigned long long u64;

// ---------------- device scratch (no dynamic allocation allowed) ------------
__device__ float g_ix[Nn * Hh];
__device__ float g_fx[Nn * Hh];
__device__ float g_ox[Nn * Hh];
__device__ float g_ux[Nn * Hh];
__device__ float g_h [Nn * Hh];
__device__ float g_hsum [Nn * Hh];   // atomically accumulated child h
__device__ float g_fcacc[Nn * Hh];   // atomically accumulated f*c
__device__ float g_pool[Bt * 8 * Hh];
__device__ int   g_kcnt[Nn];         // number of children
__device__ int   g_parent[Nn];       // parent node id, -1 for roots
__device__ int   g_level_nodes[Nn];
__device__ int   g_done[Nn];         // h-slice completion (target 8)
__device__ int   g_cnt[Nn];          // push completion (target 256*k)
__device__ int   g_cursor[8 * 32];   // one cursor per column-block, padded

// ---------------- helpers ----------------------------------------------------
__device__ __forceinline__ u64 dup2(float a) {
    u64 r; asm("mov.b64 %0,{%1,%1};" : "=l"(r) : "f"(a)); return r;
}
__device__ __forceinline__ void fma2(u64& d, u64 a, u64 b) {
    asm("fma.rn.f32x2 %0,%1,%2,%0;" : "+l"(d) : "l"(a), "l"(b));
}
__device__ __forceinline__ float red2(u64 v) {
    float a, b; asm("mov.b64 {%0,%1},%2;" : "=f"(a), "=f"(b) : "l"(v));
    return a + b;
}
__device__ __forceinline__ float lo2(u64 v) {
    float a, b; asm("mov.b64 {%0,%1},%2;" : "=f"(a), "=f"(b) : "l"(v)); return a;
}
__device__ __forceinline__ float hi2(u64 v) {
    float a, b; asm("mov.b64 {%0,%1},%2;" : "=f"(a), "=f"(b) : "l"(v)); return b;
}
__device__ __forceinline__ int ldacq(const int* p) {
    int v; asm volatile("ld.acquire.gpu.global.s32 %0,[%1];" : "=r"(v) : "l"(p) : "memory");
    return v;
}
__device__ __forceinline__ void red_release(int* p) {
    asm volatile("red.release.gpu.global.add.s32 [%0],1;" :: "l"(p) : "memory");
}
__device__ __forceinline__ void redf(float* p, float v) {
    asm volatile("red.relaxed.gpu.global.add.f32 [%0],%1;" :: "l"(p), "f"(v) : "memory");
}
__device__ __forceinline__ void waitval(const int* p, int target) {
    int it = 0;
    while (ldacq(p) != target) { if (++it > 32) __nanosleep(128); }
}
__device__ __forceinline__ float sigm(float x) { return 1.f / (1.f + __expf(-x)); }

// ---------------- zero accumulators (every launch; graph replays) -----------
__global__ void __launch_bounds__(256) zero_kernel()
{
    int i = blockIdx.x * 256 + threadIdx.x;
    float4 z = make_float4(0.f, 0.f, 0.f, 0.f);
    ((float4*)g_hsum)[i] = z;
    ((float4*)g_fcacc)[i] = z;
}

// ---------------- preprocess: counts, parents, level list -------------------
__global__ void __launch_bounds__(512) preprocess_kernel(
    const int* __restrict__ child_idx,
    const int* __restrict__ parent_idx,
    const int* __restrict__ node_height)
{
    __shared__ int s_cnt[Nn];
    __shared__ int s_lvl[NLEVc + 1];
    const int t = threadIdx.x;

    for (int i = t; i < Nn; i += 512) {
        s_cnt[i] = 0; g_done[i] = 0; g_cnt[i] = 0; g_parent[i] = -1;
    }
    if (t <= NLEVc) s_lvl[t] = 0;
    if (t < 8) g_cursor[t * 32] = 0;
    __syncthreads();

    for (int e = t; e < Ee; e += 512) {
        int p = parent_idx[e];
        atomicAdd(&s_cnt[p], 1);
        g_parent[child_idx[e]] = p;
    }
    for (int i = t; i < Nn; i += 512) atomicAdd(&s_lvl[node_height[i]], 1);
    __syncthreads();

    for (int i = t; i < Nn; i += 512) g_kcnt[i] = s_cnt[i];

    if (t == 0) {
        int acc = 0;
        for (int l = 0; l < NLEVc; l++) {
            int c = s_lvl[l];
            s_lvl[l] = acc;
            acc += c;
        }
    }
    __syncthreads();

    // level-ordered node scatter (intra-level order irrelevant)
    for (int i = t; i < Nn; i += 512) {
        int pos = atomicAdd(&s_lvl[node_height[i]], 1);
        g_level_nodes[pos] = i;
    }
}

// ---------------- fused embed + input GEMMs: x[2048,256] @ W[256,256] (x4) --
__global__ void __launch_bounds__(256) input_gemm_kernel(
    const int* __restrict__ xs, const int* __restrict__ rels,
    const float* __restrict__ embW, const float* __restrict__ relW,
    const float* __restrict__ Wix, const float* __restrict__ Wfx,
    const float* __restrict__ Wox, const float* __restrict__ Wux,
    const float* __restrict__ bix, const float* __restrict__ bfx)
{
    __shared__ __align__(16) float As[16][68];
    __shared__ __align__(16) float Bs[16][68];
    __shared__ int s_xs[64], s_rels[64];
    const int mz = blockIdx.z;
    const float* W  = (mz == 0) ? Wix : (mz == 1) ? Wfx : (mz == 2) ? Wox : Wux;
    const float* bp = (mz == 0) ? bix : (mz == 1) ? bfx : nullptr;
    float* O = (mz == 0) ? g_ix : (mz == 1) ? g_fx : (mz == 2) ? g_ox : g_ux;

    const int t = threadIdx.x;
    const int tx = t & 15, ty = t >> 4;
    const int row0 = blockIdx.y * 64, col0 = blockIdx.x * 64;
    if (t < 64) { s_xs[t] = xs[row0 + t]; s_rels[t] = rels[row0 + t]; }
    __syncthreads();

    u64 acc[4][2] = {};

    for (int kk = 0; kk < 256; kk += 16) {
        {
            int m = t >> 2, kq = (t & 3) * 4;
            int gk = kk + kq;
            float4 a;
            if (gk < DEc) a = *(const float4*)(embW + (size_t)s_xs[m] * DEc + gk);
            else          a = *(const float4*)(relW + (size_t)s_rels[m] * DRc + (gk - DEc));
            As[kq + 0][m] = a.x; As[kq + 1][m] = a.y;
            As[kq + 2][m] = a.z; As[kq + 3][m] = a.w;
            int k = t >> 4, nq = (t & 15) * 4;
            float4 b = *(const float4*)(W + (kk + k) * 256 + col0 + nq);
            *(float4*)&Bs[k][nq] = b;
        }
        __syncthreads();
#pragma unroll
        for (int k = 0; k < 16; k++) {
            float4 a = *(const float4*)&As[k][ty * 4];
            u64 b0 = *(const u64*)&Bs[k][tx * 4];
            u64 b1 = *(const u64*)&Bs[k][tx * 4 + 2];
            u64 d;
            d = dup2(a.x); fma2(acc[0][0], d, b0); fma2(acc[0][1], d, b1);
            d = dup2(a.y); fma2(acc[1][0], d, b0); fma2(acc[1][1], d, b1);
            d = dup2(a.z); fma2(acc[2][0], d, b0); fma2(acc[2][1], d, b1);
            d = dup2(a.w); fma2(acc[3][0], d, b0); fma2(acc[3][1], d, b1);
        }
        __syncthreads();
    }
    int cc0 = col0 + tx * 4;
    float4 bb = make_float4(0.f, 0.f, 0.f, 0.f);
    if (bp) bb = *(const float4*)(bp + cc0);
#pragma unroll
    for (int r = 0; r < 4; r++) {
        int row = row0 + ty * 4 + r;
        float4 o;
        o.x = lo2(acc[r][0]) + bb.x; o.y = hi2(acc[r][0]) + bb.y;
        o.z = lo2(acc[r][1]) + bb.z; o.w = hi2(acc[r][1]) + bb.w;
        *(float4*)(O + row * 256 + cc0) = o;
    }
}

// ---------------- producer-push dataflow recurrence -------------------------
// Parent waits ONE counter and reads accumulated h_sum/fc; each finished node
// pushes its own contribution (h, f*c) to its parent via global fp atomics.
__global__ void __launch_bounds__(NTH) rec_kernel(
    const float* __restrict__ Wih, const float* __restrict__ Woh,
    const float* __restrict__ Wuh, const float* __restrict__ Wfh,
    const float* __restrict__ bih_g, const float* __restrict__ bfh_g)
{
    extern __shared__ __align__(16) float sm[];
    float* Wi = sm;              // each 8192 floats, pair-interleaved over k:
    float* Wo = sm + 8192;       //   W*[k2*64 + lane*2 + s] = W[2*k2+s][cb*32+lane]
    float* Wu = sm + 16384;
    float* Wf = sm + 24576;
    float* hchAll = sm + 32768;  // 16 warps x 256

    const int t = threadIdx.x;
    const int lane = t & 31, w = t >> 5;
    const int cb = blockIdx.x & 7;
    const int col = cb * 32 + lane;

    for (int p = t; p < 4096; p += NTH) {
        int k2 = p >> 5, j = p & 31;
        int g0 = (2 * k2) * 256 + cb * 32 + j;
        int o = k2 * 64 + j * 2;
        Wi[o] = Wih[g0]; Wi[o + 1] = Wih[g0 + 256];
        Wo[o] = Woh[g0]; Wo[o + 1] = Woh[g0 + 256];
        Wu[o] = Wuh[g0]; Wu[o + 1] = Wuh[g0 + 256];
        Wf[o] = Wfh[g0]; Wf[o + 1] = Wfh[g0 + 256];
    }
    const float bih = bih_g[col];
    const float bfh = bfh_g[col];
    float* hch = hchAll + w * 256;
    const u64* Wi2 = (const u64*)Wi;
    const u64* Wo2 = (const u64*)Wo;
    const u64* Wu2 = (const u64*)Wu;
    const u64* Wf2 = (const u64*)Wf;
    __syncthreads();

    for (;;) {
        int pos;
        if (lane == 0) pos = atomicAdd(&g_cursor[cb * 32], 1);
        pos = __shfl_sync(0xffffffffu, pos, 0);
        if (pos >= Nn) break;
        int n = g_level_nodes[pos];
        int k = g_kcnt[n];
        float ixv = g_ix[n * 256 + col];
        float oxv = g_ox[n * 256 + col];
        float uxv = g_ux[n * 256 + col];
        float ov, cn;

        if (k == 0) {                               // leaf: h_sum = 0, fc = 0
            float iv = sigm(ixv + bih);
            ov = sigm(oxv);
            cn = iv * tanhf(uxv);
        } else {
            // wait for all 256*k push-arrivals, then read accumulators once
            waitval(&g_cnt[n], k << 8);
            const float* hsrow = g_hsum + n * 256;
#pragma unroll
            for (int q = 0; q < 8; q++)
                hch[q * 32 + lane] = __ldcg(hsrow + q * 32 + lane);
            float fcv = __ldcg(g_fcacc + n * 256 + col);
            __syncwarp();
            u64 i0 = 0, i1 = 0, o0 = 0, o1 = 0, u0 = 0, u1 = 0;
#pragma unroll 4
            for (int k2 = 0; k2 < 128; k2 += 2) {
                u64 p01 = *(const u64*)(hch + 2 * k2);
                u64 p23 = *(const u64*)(hch + 2 * k2 + 2);
                fma2(i0, p01, Wi2[(k2 + 0) * 32 + lane]);
                fma2(i1, p23, Wi2[(k2 + 1) * 32 + lane]);
                fma2(o0, p01, Wo2[(k2 + 0) * 32 + lane]);
                fma2(o1, p23, Wo2[(k2 + 1) * 32 + lane]);
                fma2(u0, p01, Wu2[(k2 + 0) * 32 + lane]);
                fma2(u1, p23, Wu2[(k2 + 1) * 32 + lane]);
            }
            float iv = sigm(ixv + red2(i0) + red2(i1) + bih);
            ov = sigm(oxv + red2(o0) + red2(o1));
            float uv = tanhf(uxv + red2(u0) + red2(u1));
            cn = fmaf(iv, uv, fcv);
            __syncwarp();
        }
        float hv = ov * tanhf(cn);
        __stcg(g_h + n * 256 + col, hv);
        __syncwarp();
        if (lane == 0) red_release(&g_done[n]);

        // ---- push phase: contribute to parent's accumulators ----
        int par = g_parent[n];
        if (par >= 0) {
            waitval(&g_done[n], 8);                 // all 8 col-slices of h[n]
            const float* hr = g_h + n * 256;
#pragma unroll
            for (int q = 0; q < 8; q++)
                hch[q * 32 + lane] = __ldcg(hr + q * 32 + lane);
            __syncwarp();
            u64 a0 = 0, a1 = 0, a2 = 0, a3 = 0;
#pragma unroll 8
            for (int k2 = 0; k2 < 128; k2 += 4) {
                fma2(a0, *(const u64*)(hch + 2 * k2),     Wf2[(k2 + 0) * 32 + lane]);
                fma2(a1, *(const u64*)(hch + 2 * k2 + 2), Wf2[(k2 + 1) * 32 + lane]);
                fma2(a2, *(const u64*)(hch + 2 * k2 + 4), Wf2[(k2 + 2) * 32 + lane]);
                fma2(a3, *(const u64*)(hch + 2 * k2 + 6), Wf2[(k2 + 3) * 32 + lane]);
            }
            float fd = red2(a0) + red2(a1) + red2(a2) + red2(a3);
            float f = sigm(fd + bfh + __ldcg(g_fx + par * 256 + col));
            redf(g_hsum + par * 256 + col, hv);
            redf(g_fcacc + par * 256 + col, f * cn);
            red_release(&g_cnt[par]);               // per-lane: 32 x 8 = 256/child
            __syncwarp();
        }
    }
}

// ---------------- parallel 2-stage max-pool + output ------------------------
__global__ void __launch_bounds__(256) pool1_kernel()
{
    int b = blockIdx.x, chn = blockIdx.y, t = threadIdx.x;
    const float* hb = g_h + ((size_t)b * St + chn * 16) * Hh;
    float m = -1e30f;
#pragma unroll
    for (int s2 = 0; s2 < 16; s2++) m = fmaxf(m, hb[s2 * Hh + t]);
    g_pool[(b * 8 + chn) * Hh + t] = m;
}

__global__ void __launch_bounds__(256) pool2_kernel(
    const float* __restrict__ Wout, const float* __restrict__ bout,
    float* __restrict__ out)
{
    __shared__ float pooled[Hh];
    int b = blockIdx.x, t = threadIdx.x;
    float m = -1e30f;
#pragma unroll
    for (int chn = 0; chn < 8; chn++)
        m = fmaxf(m, g_pool[(b * 8 + chn) * Hh + t]);
    pooled[t] = m;
    __syncthreads();
    if (t < Lc) {
        float acc = bout[t];
        for (int k = 0; k < Hh; k++) acc = fmaf(pooled[k], Wout[k * Lc + t], acc);
        out[b * Lc + t] = acc;
    }
}

// ---------------- host-side launch ------------------------------------------
extern "C" void kernel_launch(void* const* d_in, const int* in_sizes, int n_in,
                              void* d_out, int out_size)
{
    int off = (in_sizes[5] == 1) ? 6 : 5;

    const int* xs        = (const int*)d_in[0];
    const int* rels      = (const int*)d_in[1];
    const int* child_idx = (const int*)d_in[2];
    const int* parent_idx= (const int*)d_in[3];
    const int* height    = (const int*)d_in[4];
    const float* embW  = (const float*)d_in[off + 0];
    const float* relW  = (const float*)d_in[off + 1];
    const float* W_ix  = (const float*)d_in[off + 2];
    const float* b_ix  = (const float*)d_in[off + 3];
    const float* W_ih  = (const float*)d_in[off + 4];
    const float* b_ih  = (const float*)d_in[off + 5];
    const float* W_fx  = (const float*)d_in[off + 6];
    const float* b_fx  = (const float*)d_in[off + 7];
    const float* W_fh  = (const float*)d_in[off + 8];
    const float* b_fh  = (const float*)d_in[off + 9];
    const float* W_ox  = (const float*)d_in[off + 10];
    const float* W_oh  = (const float*)d_in[off + 11];
    const float* W_ux  = (const float*)d_in[off + 12];
    const float* W_uh  = (const float*)d_in[off + 13];
    const float* W_out = (const float*)d_in[off + 14];
    const float* b_out = (const float*)d_in[off + 15];

    cudaFuncSetAttribute(rec_kernel,
                         cudaFuncAttributeMaxDynamicSharedMemorySize, 163840);

    zero_kernel<<<512, 256>>>();
    preprocess_kernel<<<1, 512>>>(child_idx, parent_idx, height);
    dim3 gg(4, 32, 4);
    input_gemm_kernel<<<gg, 256>>>(xs, rels, embW, relW,
                                   W_ix, W_fx, W_ox, W_ux, b_ix, b_fx);
    rec_kernel<<<NCTA, NTH, 163840>>>(W_ih, W_oh, W_uh, W_fh, b_ih, b_fh);
    pool1_kernel<<<dim3(16, 8), 256>>>();
    pool2_kernel<<<Bt, 256>>>(W_out, b_out, (float*)d_out);
}

// round 13
// speedup vs baseline: 1.8540x; 1.7439x over previous
#include <cuda_runtime.h>
#include <math.h>

#define Bt    16
#define St    128
#define Nn    2048
#define Ee    2032
#define Hh    256
#define DEc   192
#define DRc   64
#define Lc    12
#define NLEVc 21
#define NCTA  144
#define NTH   512

typedef unsigned long long u64;

// ---------------- device scratch (no dynamic allocation allowed) ------------
__device__ float g_ix[Nn * Hh];
__device__ float g_fx[Nn * Hh];
__device__ float g_ox[Nn * Hh];
__device__ float g_ux[Nn * Hh];
__device__ float g_h [Nn * Hh];
__device__ float g_c [Nn * Hh];
__device__ float g_pool[Bt * 8 * Hh];
__device__ int   g_child_start[Nn + 1];
__device__ int   g_child_list [Ee];
__device__ int   g_level_nodes[Nn];
__device__ int   g_done[Nn];
__device__ int   g_nleaf;
__device__ int   g_curL[8 * 32];     // leaf cursor per column-block
__device__ int   g_curI[8 * 32];     // interior cursor per column-block

// ---------------- helpers ----------------------------------------------------
__device__ __forceinline__ u64 dup2(float a) {
    u64 r; asm("mov.b64 %0,{%1,%1};" : "=l"(r) : "f"(a)); return r;
}
__device__ __forceinline__ void fma2(u64& d, u64 a, u64 b) {
    asm("fma.rn.f32x2 %0,%1,%2,%0;" : "+l"(d) : "l"(a), "l"(b));
}
__device__ __forceinline__ float red2(u64 v) {
    float a, b; asm("mov.b64 {%0,%1},%2;" : "=f"(a), "=f"(b) : "l"(v));
    return a + b;
}
__device__ __forceinline__ float lo2(u64 v) {
    float a, b; asm("mov.b64 {%0,%1},%2;" : "=f"(a), "=f"(b) : "l"(v)); return a;
}
__device__ __forceinline__ float hi2(u64 v) {
    float a, b; asm("mov.b64 {%0,%1},%2;" : "=f"(a), "=f"(b) : "l"(v)); return b;
}
__device__ __forceinline__ int ldacq(const int* p) {
    int v; asm volatile("ld.acquire.gpu.global.s32 %0,[%1];" : "=r"(v) : "l"(p) : "memory");
    return v;
}
__device__ __forceinline__ void red_release(int* p) {
    asm volatile("red.release.gpu.global.add.s32 [%0],1;" :: "l"(p) : "memory");
}
__device__ __forceinline__ void waitdone(const int* p) {
    int it = 0;
    while (ldacq(p) != 8) { if (++it > 200) __nanosleep(64); }
}
__device__ __forceinline__ float sigm(float x) { return 1.f / (1.f + __expf(-x)); }

// ---------------- init: zero done flags (launch #1) -------------------------
__global__ void __launch_bounds__(256) init_kernel()
{
    int i = blockIdx.x * 256 + threadIdx.x;
    if (i < Nn) g_done[i] = 0;
}

// ---------------- preprocess: child CSR + level lists + cursors -------------
__global__ void __launch_bounds__(512) preprocess_kernel(
    const int* __restrict__ child_idx,
    const int* __restrict__ parent_idx,
    const int* __restrict__ node_height)
{
    __shared__ int s_cnt[Nn];
    __shared__ int s_aux[512];
    __shared__ int s_par[Ee];
    __shared__ int s_lvl[NLEVc + 1];
    const int t = threadIdx.x;

    for (int i = t; i < Nn; i += 512) s_cnt[i] = 0;
    for (int e = t; e < Ee; e += 512) s_par[e] = parent_idx[e];
    if (t <= NLEVc) s_lvl[t] = 0;
    __syncthreads();

    for (int e = t; e < Ee; e += 512) atomicAdd(&s_cnt[s_par[e]], 1);
    for (int i = t; i < Nn; i += 512) atomicAdd(&s_lvl[node_height[i]], 1);
    __syncthreads();

    int v[4]; int s = 0;
#pragma unroll
    for (int r = 0; r < 4; r++) { v[r] = s_cnt[t * 4 + r]; s += v[r]; }
    s_aux[t] = s;
    __syncthreads();
    for (int off = 1; off < 512; off <<= 1) {
        int x = (t >= off) ? s_aux[t - off] : 0;
        __syncthreads();
        s_aux[t] += x;
        __syncthreads();
    }
    int run = (t == 0) ? 0 : s_aux[t - 1];
#pragma unroll
    for (int r = 0; r < 4; r++) {
        int c = v[r];
        g_child_start[t * 4 + r] = run;
        s_cnt[t * 4 + r] = run;
        run += c;
    }
    if (t == 511) g_child_start[Nn] = run;
    __syncthreads();

    if (t == 0) {
        int acc = 0;
        for (int l = 0; l < NLEVc; l++) {
            int c = s_lvl[l];
            s_lvl[l] = acc;
            acc += c;
        }
        int nleaf = s_lvl[1];              // level-0 count = #leaves
        g_nleaf = nleaf;
        for (int i = 0; i < 8; i++) { g_curL[i * 32] = 0; g_curI[i * 32] = nleaf; }
    }
    __syncthreads();

    // warp-per-tree child scatter: rank = #earlier same-parent edges in tree
    {
        int w = t >> 5, lane = t & 31;
        if (w < Bt) {
            int e0 = w * (St - 1);
            for (int el = lane; el < St - 1; el += 32) {
                int e = e0 + el;
                int p = s_par[e];
                int rank = 0;
                for (int e2 = e0; e2 < e; ++e2) rank += (s_par[e2] == p) ? 1 : 0;
                g_child_list[s_cnt[p] + rank] = child_idx[e];
            }
        }
    }
    // level-node scatter (intra-level order irrelevant)
    for (int i = t; i < Nn; i += 512) {
        int pos = atomicAdd(&s_lvl[node_height[i]], 1);
        g_level_nodes[pos] = i;
    }
}

// ---------------- fused embed + input GEMMs: x[2048,256] @ W[256,256] (x4) --
__global__ void __launch_bounds__(256) input_gemm_kernel(
    const int* __restrict__ xs, const int* __restrict__ rels,
    const float* __restrict__ embW, const float* __restrict__ relW,
    const float* __restrict__ Wix, const float* __restrict__ Wfx,
    const float* __restrict__ Wox, const float* __restrict__ Wux,
    const float* __restrict__ bix, const float* __restrict__ bfx)
{
    __shared__ __align__(16) float As[16][68];
    __shared__ __align__(16) float Bs[16][68];
    __shared__ int s_xs[64], s_rels[64];
    const int mz = blockIdx.z;
    const float* W  = (mz == 0) ? Wix : (mz == 1) ? Wfx : (mz == 2) ? Wox : Wux;
    const float* bp = (mz == 0) ? bix : (mz == 1) ? bfx : nullptr;
    float* O = (mz == 0) ? g_ix : (mz == 1) ? g_fx : (mz == 2) ? g_ox : g_ux;

    const int t = threadIdx.x;
    const int tx = t & 15, ty = t >> 4;
    const int row0 = blockIdx.y * 64, col0 = blockIdx.x * 64;
    if (t < 64) { s_xs[t] = xs[row0 + t]; s_rels[t] = rels[row0 + t]; }
    __syncthreads();

    u64 acc[4][2] = {};

    for (int kk = 0; kk < 256; kk += 16) {
        {
            int m = t >> 2, kq = (t & 3) * 4;
            int gk = kk + kq;
            float4 a;
            if (gk < DEc) a = *(const float4*)(embW + (size_t)s_xs[m] * DEc + gk);
            else          a = *(const float4*)(relW + (size_t)s_rels[m] * DRc + (gk - DEc));
            As[kq + 0][m] = a.x; As[kq + 1][m] = a.y;
            As[kq + 2][m] = a.z; As[kq + 3][m] = a.w;
            int k = t >> 4, nq = (t & 15) * 4;
            float4 b = *(const float4*)(W + (kk + k) * 256 + col0 + nq);
            *(float4*)&Bs[k][nq] = b;
        }
        __syncthreads();
#pragma unroll
        for (int k = 0; k < 16; k++) {
            float4 a = *(const float4*)&As[k][ty * 4];
            u64 b0 = *(const u64*)&Bs[k][tx * 4];
            u64 b1 = *(const u64*)&Bs[k][tx * 4 + 2];
            u64 d;
            d = dup2(a.x); fma2(acc[0][0], d, b0); fma2(acc[0][1], d, b1);
            d = dup2(a.y); fma2(acc[1][0], d, b0); fma2(acc[1][1], d, b1);
            d = dup2(a.z); fma2(acc[2][0], d, b0); fma2(acc[2][1], d, b1);
            d = dup2(a.w); fma2(acc[3][0], d, b0); fma2(acc[3][1], d, b1);
        }
        __syncthreads();
    }
    int cc0 = col0 + tx * 4;
    float4 bb = make_float4(0.f, 0.f, 0.f, 0.f);
    if (bp) bb = *(const float4*)(bp + cc0);
#pragma unroll
    for (int r = 0; r < 4; r++) {
        int row = row0 + ty * 4 + r;
        float4 o;
        o.x = lo2(acc[r][0]) + bb.x; o.y = hi2(acc[r][0]) + bb.y;
        o.z = lo2(acc[r][1]) + bb.z; o.w = hi2(acc[r][1]) + bb.w;
        *(float4*)(O + row * 256 + cc0) = o;
    }
}

// ---------------- dataflow recurrence: leaf fast-path + interior pull -------
__global__ void __launch_bounds__(NTH) rec_kernel(
    const float* __restrict__ Wih, const float* __restrict__ Woh,
    const float* __restrict__ Wuh, const float* __restrict__ Wfh,
    const float* __restrict__ bih_g, const float* __restrict__ bfh_g)
{
    extern __shared__ __align__(16) float sm[];
    float* Wi = sm;              // each 8192 floats, pair-interleaved over k:
    float* Wo = sm + 8192;       //   W*[k2*64 + lane*2 + s] = W[2*k2+s][cb*32+lane]
    float* Wu = sm + 16384;
    float* Wf = sm + 24576;
    float* hchAll = sm + 32768;  // 16 warps x 256

    const int t = threadIdx.x;
    const int lane = t & 31, w = t >> 5;
    const int cb = blockIdx.x & 7;
    const int col = cb * 32 + lane;

    for (int p = t; p < 4096; p += NTH) {
        int k2 = p >> 5, j = p & 31;
        int g0 = (2 * k2) * 256 + cb * 32 + j;
        int o = k2 * 64 + j * 2;
        Wi[o] = Wih[g0]; Wi[o + 1] = Wih[g0 + 256];
        Wo[o] = Woh[g0]; Wo[o + 1] = Woh[g0 + 256];
        Wu[o] = Wuh[g0]; Wu[o + 1] = Wuh[g0 + 256];
        Wf[o] = Wfh[g0]; Wf[o + 1] = Wfh[g0 + 256];
    }
    const float bih = bih_g[col];
    const float bfh = bfh_g[col];
    float* hch = hchAll + w * 256;
    const u64* Wi2 = (const u64*)Wi;
    const u64* Wo2 = (const u64*)Wo;
    const u64* Wu2 = (const u64*)Wu;
    const u64* Wf2 = (const u64*)Wf;
    __syncthreads();

    // ---------------- leaf phase: no dependencies, quad grabs ----------------
    const int nleaf = g_nleaf;
    for (;;) {
        int pos;
        if (lane == 0) pos = atomicAdd(&g_curL[cb * 32], 4);
        pos = __shfl_sync(0xffffffffu, pos, 0);
        if (pos >= nleaf) break;
        int lim = (pos + 4 < nleaf) ? pos + 4 : nleaf;
        for (int p2 = pos; p2 < lim; p2++) {
            int n = g_level_nodes[p2];
            float ixv = __ldcg(g_ix + n * 256 + col);
            float oxv = __ldcg(g_ox + n * 256 + col);
            float uxv = __ldcg(g_ux + n * 256 + col);
            float iv = sigm(ixv + bih);
            float ov = sigm(oxv);
            float cn = iv * tanhf(uxv);
            __stcg(g_c + n * 256 + col, cn);
            __stcg(g_h + n * 256 + col, ov * tanhf(cn));
            __syncwarp();
            if (lane == 0) red_release(&g_done[n]);
        }
    }

    // ---------------- interior phase: pull with child prefetch --------------
    for (;;) {
        int pos;
        if (lane == 0) pos = atomicAdd(&g_curI[cb * 32], 1);
        pos = __shfl_sync(0xffffffffu, pos, 0);
        if (pos >= Nn) break;
        int n = g_level_nodes[pos];
        int cs0 = g_child_start[n], cs1 = g_child_start[n + 1];
        float ixv = g_ix[n * 256 + col];
        float oxv = g_ox[n * 256 + col];
        float uxv = g_ux[n * 256 + col];
        float fxn = g_fx[n * 256 + col];

        float rs[8];
#pragma unroll
        for (int q = 0; q < 8; q++) rs[q] = 0.f;
        float fc = 0.f;
        float hreg[8], cpre;

        // prologue: wait + load first child into registers
        {
            int ch = g_child_list[cs0];
            waitdone(&g_done[ch]);
            const float* hrow = g_h + ch * 256;
#pragma unroll
            for (int q = 0; q < 8; q++) hreg[q] = __ldcg(hrow + q * 32 + lane);
            cpre = __ldcg(g_c + ch * 256 + col);
        }

        for (int e = cs0; e < cs1; e++) {
            // commit current child to smem + running sum
#pragma unroll
            for (int q = 0; q < 8; q++) {
                hch[q * 32 + lane] = hreg[q];
                rs[q] += hreg[q];
            }
            float ccur = cpre;
            __syncwarp();
            // prefetch next child (loads overlap the f-dot below)
            if (e + 1 < cs1) {
                int ch = g_child_list[e + 1];
                waitdone(&g_done[ch]);
                const float* hrow = g_h + ch * 256;
#pragma unroll
                for (int q = 0; q < 8; q++) hreg[q] = __ldcg(hrow + q * 32 + lane);
                cpre = __ldcg(g_c + ch * 256 + col);
            }
            // f-dot over committed child (from smem)
            u64 a0 = 0, a1 = 0, a2 = 0, a3 = 0;
#pragma unroll 8
            for (int k2 = 0; k2 < 128; k2 += 4) {
                fma2(a0, *(const u64*)(hch + 2 * k2),     Wf2[(k2 + 0) * 32 + lane]);
                fma2(a1, *(const u64*)(hch + 2 * k2 + 2), Wf2[(k2 + 1) * 32 + lane]);
                fma2(a2, *(const u64*)(hch + 2 * k2 + 4), Wf2[(k2 + 2) * 32 + lane]);
                fma2(a3, *(const u64*)(hch + 2 * k2 + 6), Wf2[(k2 + 3) * 32 + lane]);
            }
            float fd = red2(a0) + red2(a1) + red2(a2) + red2(a3);
            float f = sigm(fd + bfh + fxn);
            fc = fmaf(f, ccur, fc);
            __syncwarp();
        }

        // h_sum -> smem (broadcast source for i/o/u dots)
#pragma unroll
        for (int q = 0; q < 8; q++) hch[q * 32 + lane] = rs[q];
        __syncwarp();
        u64 i0 = 0, i1 = 0, o0 = 0, o1 = 0, u0 = 0, u1 = 0;
#pragma unroll 4
        for (int k2 = 0; k2 < 128; k2 += 2) {
            u64 p01 = *(const u64*)(hch + 2 * k2);
            u64 p23 = *(const u64*)(hch + 2 * k2 + 2);
            fma2(i0, p01, Wi2[(k2 + 0) * 32 + lane]);
            fma2(i1, p23, Wi2[(k2 + 1) * 32 + lane]);
            fma2(o0, p01, Wo2[(k2 + 0) * 32 + lane]);
            fma2(o1, p23, Wo2[(k2 + 1) * 32 + lane]);
            fma2(u0, p01, Wu2[(k2 + 0) * 32 + lane]);
            fma2(u1, p23, Wu2[(k2 + 1) * 32 + lane]);
        }
        float iv = sigm(ixv + red2(i0) + red2(i1) + bih);
        float ov = sigm(oxv + red2(o0) + red2(o1));
        float uv = tanhf(uxv + red2(u0) + red2(u1));
        float cn = fmaf(iv, uv, fc);
        __syncwarp();

        __stcg(g_c + n * 256 + col, cn);
        __stcg(g_h + n * 256 + col, ov * tanhf(cn));
        __syncwarp();
        if (lane == 0) red_release(&g_done[n]);
    }
}

// ---------------- parallel 2-stage max-pool + output ------------------------
__global__ void __launch_bounds__(256) pool1_kernel()
{
    int b = blockIdx.x, chn = blockIdx.y, t = threadIdx.x;
    const float* hb = g_h + ((size_t)b * St + chn * 16) * Hh;
    float m = -1e30f;
#pragma unroll
    for (int s2 = 0; s2 < 16; s2++) m = fmaxf(m, hb[s2 * Hh + t]);
    g_pool[(b * 8 + chn) * Hh + t] = m;
}

__global__ void __launch_bounds__(256) pool2_kernel(
    const float* __restrict__ Wout, const float* __restrict__ bout,
    float* __restrict__ out)
{
    __shared__ float pooled[Hh];
    int b = blockIdx.x, t = threadIdx.x;
    float m = -1e30f;
#pragma unroll
    for (int chn = 0; chn < 8; chn++)
        m = fmaxf(m, g_pool[(b * 8 + chn) * Hh + t]);
    pooled[t] = m;
    __syncthreads();
    if (t < Lc) {
        float acc = bout[t];
        for (int k = 0; k < Hh; k++) acc = fmaf(pooled[k], Wout[k * Lc + t], acc);
        out[b * Lc + t] = acc;
    }
}

// ---------------- host-side launch ------------------------------------------
extern "C" void kernel_launch(void* const* d_in, const int* in_sizes, int n_in,
                              void* d_out, int out_size)
{
    int off = (in_sizes[5] == 1) ? 6 : 5;

    const int* xs        = (const int*)d_in[0];
    const int* rels      = (const int*)d_in[1];
    const int* child_idx = (const int*)d_in[2];
    const int* parent_idx= (const int*)d_in[3];
    const int* height    = (const int*)d_in[4];
    const float* embW  = (const float*)d_in[off + 0];
    const float* relW  = (const float*)d_in[off + 1];
    const float* W_ix  = (const float*)d_in[off + 2];
    const float* b_ix  = (const float*)d_in[off + 3];
    const float* W_ih  = (const float*)d_in[off + 4];
    const float* b_ih  = (const float*)d_in[off + 5];
    const float* W_fx  = (const float*)d_in[off + 6];
    const float* b_fx  = (const float*)d_in[off + 7];
    const float* W_fh  = (const float*)d_in[off + 8];
    const float* b_fh  = (const float*)d_in[off + 9];
    const float* W_ox  = (const float*)d_in[off + 10];
    const float* W_oh  = (const float*)d_in[off + 11];
    const float* W_ux  = (const float*)d_in[off + 12];
    const float* W_uh  = (const float*)d_in[off + 13];
    const float* W_out = (const float*)d_in[off + 14];
    const float* b_out = (const float*)d_in[off + 15];

    cudaFuncSetAttribute(rec_kernel,
                         cudaFuncAttributeMaxDynamicSharedMemorySize, 147456);

    init_kernel<<<8, 256>>>();
    preprocess_kernel<<<1, 512>>>(child_idx, parent_idx, height);
    dim3 gg(4, 32, 4);
    input_gemm_kernel<<<gg, 256>>>(xs, rels, embW, relW,
                                   W_ix, W_fx, W_ox, W_ux, b_ix, b_fx);
    rec_kernel<<<NCTA, NTH, 147456>>>(W_ih, W_oh, W_uh, W_fh, b_ih, b_fh);
    pool1_kernel<<<dim3(16, 8), 256>>>();
    pool2_kernel<<<Bt, 256>>>(W_out, b_out, (float*)d_out);
}

// round 15
// speedup vs baseline: 1.8565x; 1.0013x over previous
#include <cuda_runtime.h>
#include <math.h>

#define Bt    16
#define St    128
#define Nn    2048
#define Ee    2032
#define Hh    256
#define DEc   192
#define DRc   64
#define Lc    12
#define NLEVc 21
#define NCTA  144
#define NTH   512

typedef unsigned long long u64;

// ---------------- device scratch (no dynamic allocation allowed) ------------
__device__ float g_ix[Nn * Hh];
__device__ float g_fx[Nn * Hh];
__device__ float g_ox[Nn * Hh];
__device__ float g_ux[Nn * Hh];
__device__ float g_h [Nn * Hh];
__device__ float g_c [Nn * Hh];
__device__ float g_pool[Bt * 8 * Hh];
__device__ int   g_child_start[Nn + 1];
__device__ int   g_child_list [Ee];
__device__ int   g_level_nodes[Nn];
__device__ int   g_done[Nn];
__device__ int   g_nleaf;
__device__ int   g_curL[8 * 32];     // leaf cursor per column-block
__device__ int   g_curI[8 * 32];     // interior cursor per column-block

// ---------------- helpers ----------------------------------------------------
__device__ __forceinline__ u64 dup2(float a) {
    u64 r; asm("mov.b64 %0,{%1,%1};" : "=l"(r) : "f"(a)); return r;
}
__device__ __forceinline__ void fma2(u64& d, u64 a, u64 b) {
    asm("fma.rn.f32x2 %0,%1,%2,%0;" : "+l"(d) : "l"(a), "l"(b));
}
__device__ __forceinline__ float red2(u64 v) {
    float a, b; asm("mov.b64 {%0,%1},%2;" : "=f"(a), "=f"(b) : "l"(v));
    return a + b;
}
__device__ __forceinline__ float lo2(u64 v) {
    float a, b; asm("mov.b64 {%0,%1},%2;" : "=f"(a), "=f"(b) : "l"(v)); return a;
}
__device__ __forceinline__ float hi2(u64 v) {
    float a, b; asm("mov.b64 {%0,%1},%2;" : "=f"(a), "=f"(b) : "l"(v)); return b;
}
__device__ __forceinline__ int ldacq(const int* p) {
    int v; asm volatile("ld.acquire.gpu.global.s32 %0,[%1];" : "=r"(v) : "l"(p) : "memory");
    return v;
}
__device__ __forceinline__ void red_release(int* p) {
    asm volatile("red.release.gpu.global.add.s32 [%0],1;" :: "l"(p) : "memory");
}
__device__ __forceinline__ void waitdone(const int* p) {
    int it = 0;
    while (ldacq(p) != 8) { if (++it > 200) __nanosleep(64); }
}
__device__ __forceinline__ float sigm(float x) { return 1.f / (1.f + __expf(-x)); }

// ---------------- preprocess: flags + child CSR + level lists + cursors -----
__global__ void __launch_bounds__(512) preprocess_kernel(
    const int* __restrict__ child_idx,
    const int* __restrict__ parent_idx,
    const int* __restrict__ node_height)
{
    __shared__ int s_cnt[Nn];
    __shared__ int s_aux[512];
    __shared__ int s_par[Ee];
    __shared__ int s_lvl[NLEVc + 1];
    const int t = threadIdx.x;

    for (int i = t; i < Nn; i += 512) { s_cnt[i] = 0; g_done[i] = 0; }
    for (int e = t; e < Ee; e += 512) s_par[e] = parent_idx[e];
    if (t <= NLEVc) s_lvl[t] = 0;
    __syncthreads();

    for (int e = t; e < Ee; e += 512) atomicAdd(&s_cnt[s_par[e]], 1);
    for (int i = t; i < Nn; i += 512) atomicAdd(&s_lvl[node_height[i]], 1);
    __syncthreads();

    int v[4]; int s = 0;
#pragma unroll
    for (int r = 0; r < 4; r++) { v[r] = s_cnt[t * 4 + r]; s += v[r]; }
    s_aux[t] = s;
    __syncthreads();
    for (int off = 1; off < 512; off <<= 1) {
        int x = (t >= off) ? s_aux[t - off] : 0;
        __syncthreads();
        s_aux[t] += x;
        __syncthreads();
    }
    int run = (t == 0) ? 0 : s_aux[t - 1];
#pragma unroll
    for (int r = 0; r < 4; r++) {
        int c = v[r];
        g_child_start[t * 4 + r] = run;
        s_cnt[t * 4 + r] = run;
        run += c;
    }
    if (t == 511) g_child_start[Nn] = run;
    __syncthreads();

    if (t == 0) {
        int acc = 0;
        for (int l = 0; l < NLEVc; l++) {
            int c = s_lvl[l];
            s_lvl[l] = acc;
            acc += c;
        }
        int nleaf = s_lvl[1];              // level-0 count = #leaves
        g_nleaf = nleaf;
        for (int i = 0; i < 8; i++) { g_curL[i * 32] = 0; g_curI[i * 32] = nleaf; }
    }
    __syncthreads();

    // warp-per-tree child scatter: rank = #earlier same-parent edges in tree
    {
        int w = t >> 5, lane = t & 31;
        if (w < Bt) {
            int e0 = w * (St - 1);
            for (int el = lane; el < St - 1; el += 32) {
                int e = e0 + el;
                int p = s_par[e];
                int rank = 0;
                for (int e2 = e0; e2 < e; ++e2) rank += (s_par[e2] == p) ? 1 : 0;
                g_child_list[s_cnt[p] + rank] = child_idx[e];
            }
        }
    }
    // level-node scatter (intra-level order irrelevant)
    for (int i = t; i < Nn; i += 512) {
        int pos = atomicAdd(&s_lvl[node_height[i]], 1);
        g_level_nodes[pos] = i;
    }
}

// ---------------- fused embed + input GEMMs: x[2048,256] @ W[256,256] (x4) --
__global__ void __launch_bounds__(256) input_gemm_kernel(
    const int* __restrict__ xs, const int* __restrict__ rels,
    const float* __restrict__ embW, const float* __restrict__ relW,
    const float* __restrict__ Wix, const float* __restrict__ Wfx,
    const float* __restrict__ Wox, const float* __restrict__ Wux,
    const float* __restrict__ bix, const float* __restrict__ bfx)
{
    __shared__ __align__(16) float As[16][68];
    __shared__ __align__(16) float Bs[16][68];
    __shared__ int s_xs[64], s_rels[64];
    const int mz = blockIdx.z;
    const float* W  = (mz == 0) ? Wix : (mz == 1) ? Wfx : (mz == 2) ? Wox : Wux;
    const float* bp = (mz == 0) ? bix : (mz == 1) ? bfx : nullptr;
    float* O = (mz == 0) ? g_ix : (mz == 1) ? g_fx : (mz == 2) ? g_ox : g_ux;

    const int t = threadIdx.x;
    const int tx = t & 15, ty = t >> 4;
    const int row0 = blockIdx.y * 64, col0 = blockIdx.x * 64;
    if (t < 64) { s_xs[t] = xs[row0 + t]; s_rels[t] = rels[row0 + t]; }
    __syncthreads();

    u64 acc[4][2] = {};

    for (int kk = 0; kk < 256; kk += 16) {
        {
            int m = t >> 2, kq = (t & 3) * 4;
            int gk = kk + kq;
            float4 a;
            if (gk < DEc) a = *(const float4*)(embW + (size_t)s_xs[m] * DEc + gk);
            else          a = *(const float4*)(relW + (size_t)s_rels[m] * DRc + (gk - DEc));
            As[kq + 0][m] = a.x; As[kq + 1][m] = a.y;
            As[kq + 2][m] = a.z; As[kq + 3][m] = a.w;
            int k = t >> 4, nq = (t & 15) * 4;
            float4 b = *(const float4*)(W + (kk + k) * 256 + col0 + nq);
            *(float4*)&Bs[k][nq] = b;
        }
        __syncthreads();
#pragma unroll
        for (int k = 0; k < 16; k++) {
            float4 a = *(const float4*)&As[k][ty * 4];
            u64 b0 = *(const u64*)&Bs[k][tx * 4];
            u64 b1 = *(const u64*)&Bs[k][tx * 4 + 2];
            u64 d;
            d = dup2(a.x); fma2(acc[0][0], d, b0); fma2(acc[0][1], d, b1);
            d = dup2(a.y); fma2(acc[1][0], d, b0); fma2(acc[1][1], d, b1);
            d = dup2(a.z); fma2(acc[2][0], d, b0); fma2(acc[2][1], d, b1);
            d = dup2(a.w); fma2(acc[3][0], d, b0); fma2(acc[3][1], d, b1);
        }
        __syncthreads();
    }
    int cc0 = col0 + tx * 4;
    float4 bb = make_float4(0.f, 0.f, 0.f, 0.f);
    if (bp) bb = *(const float4*)(bp + cc0);
#pragma unroll
    for (int r = 0; r < 4; r++) {
        int row = row0 + ty * 4 + r;
        float4 o;
        o.x = lo2(acc[r][0]) + bb.x; o.y = hi2(acc[r][0]) + bb.y;
        o.z = lo2(acc[r][1]) + bb.z; o.w = hi2(acc[r][1]) + bb.w;
        *(float4*)(O + row * 256 + cc0) = o;
    }
}

// ---------------- dataflow recurrence: leaf fast-path + paired-child pull ---
__global__ void __launch_bounds__(NTH) rec_kernel(
    const float* __restrict__ Wih, const float* __restrict__ Woh,
    const float* __restrict__ Wuh, const float* __restrict__ Wfh,
    const float* __restrict__ bih_g, const float* __restrict__ bfh_g)
{
    extern __shared__ __align__(16) float sm[];
    float* Wi = sm;              // each 8192 floats, pair-interleaved over k:
    float* Wo = sm + 8192;       //   W*[k2*64 + lane*2 + s] = W[2*k2+s][cb*32+lane]
    float* Wu = sm + 16384;
    float* Wf = sm + 24576;
    float* hAll = sm + 32768;    // 16 warps x 512 (two child buffers per warp)

    const int t = threadIdx.x;
    const int lane = t & 31, w = t >> 5;
    const int cb = blockIdx.x & 7;
    const int col = cb * 32 + lane;

    for (int p = t; p < 4096; p += NTH) {
        int k2 = p >> 5, j = p & 31;
        int g0 = (2 * k2) * 256 + cb * 32 + j;
        int o = k2 * 64 + j * 2;
        Wi[o] = Wih[g0]; Wi[o + 1] = Wih[g0 + 256];
        Wo[o] = Woh[g0]; Wo[o + 1] = Woh[g0 + 256];
        Wu[o] = Wuh[g0]; Wu[o + 1] = Wuh[g0 + 256];
        Wf[o] = Wfh[g0]; Wf[o + 1] = Wfh[g0 + 256];
    }
    const float bih = bih_g[col];
    const float bfh = bfh_g[col];
    float* hA = hAll + w * 512;
    float* hB = hA + 256;
    const u64* Wi2 = (const u64*)Wi;
    const u64* Wo2 = (const u64*)Wo;
    const u64* Wu2 = (const u64*)Wu;
    const u64* Wf2 = (const u64*)Wf;
    __syncthreads();

    // ---------------- leaf phase: no dependencies, quad grabs ----------------
    const int nleaf = g_nleaf;
    for (;;) {
        int pos;
        if (lane == 0) pos = atomicAdd(&g_curL[cb * 32], 4);
        pos = __shfl_sync(0xffffffffu, pos, 0);
        if (pos >= nleaf) break;
        int lim = (pos + 4 < nleaf) ? pos + 4 : nleaf;
        for (int p2 = pos; p2 < lim; p2++) {
            int n = g_level_nodes[p2];
            float ixv = __ldcg(g_ix + n * 256 + col);
            float oxv = __ldcg(g_ox + n * 256 + col);
            float uxv = __ldcg(g_ux + n * 256 + col);
            float iv = sigm(ixv + bih);
            float ov = sigm(oxv);
            float cn = iv * tanhf(uxv);
            __stcg(g_c + n * 256 + col, cn);
            __stcg(g_h + n * 256 + col, ov * tanhf(cn));
            __syncwarp();
            if (lane == 0) red_release(&g_done[n]);
        }
    }

    // ---------------- interior phase: paired-child pull ---------------------
    for (;;) {
        int pos;
        if (lane == 0) pos = atomicAdd(&g_curI[cb * 32], 1);
        pos = __shfl_sync(0xffffffffu, pos, 0);
        if (pos >= Nn) break;
        int n = g_level_nodes[pos];
        int cs0 = g_child_start[n], cs1 = g_child_start[n + 1];
        float ixv = g_ix[n * 256 + col];
        float oxv = g_ox[n * 256 + col];
        float uxv = g_ux[n * 256 + col];
        float fxn = g_fx[n * 256 + col];

        float rs[8];
#pragma unroll
        for (int q = 0; q < 8; q++) rs[q] = 0.f;
        float fc = 0.f;
        float hrA[8], hrB[8], cApre = 0.f, cBpre = 0.f;

        // prologue: prefetch first pair into registers
        {
            int ch = g_child_list[cs0];
            waitdone(&g_done[ch]);
            const float* hr = g_h + ch * 256;
#pragma unroll
            for (int q = 0; q < 8; q++) hrA[q] = __ldcg(hr + q * 32 + lane);
            cApre = __ldcg(g_c + ch * 256 + col);
        }
        if (cs0 + 1 < cs1) {
            int ch = g_child_list[cs0 + 1];
            waitdone(&g_done[ch]);
            const float* hr = g_h + ch * 256;
#pragma unroll
            for (int q = 0; q < 8; q++) hrB[q] = __ldcg(hr + q * 32 + lane);
            cBpre = __ldcg(g_c + ch * 256 + col);
        }

        for (int e = cs0; e < cs1; e += 2) {
            bool pair = (e + 1 < cs1);
            // commit prefetched pair to smem + running sum
#pragma unroll
            for (int q = 0; q < 8; q++) { hA[q * 32 + lane] = hrA[q]; rs[q] += hrA[q]; }
            float cA = cApre, cB = 0.f;
            if (pair) {
#pragma unroll
                for (int q = 0; q < 8; q++) { hB[q * 32 + lane] = hrB[q]; rs[q] += hrB[q]; }
                cB = cBpre;
            }
            __syncwarp();
            // prefetch next pair (overlaps the joint f-dot below)
            int en = e + 2;
            if (en < cs1) {
                int ch = g_child_list[en];
                waitdone(&g_done[ch]);
                const float* hr = g_h + ch * 256;
#pragma unroll
                for (int q = 0; q < 8; q++) hrA[q] = __ldcg(hr + q * 32 + lane);
                cApre = __ldcg(g_c + ch * 256 + col);
                if (en + 1 < cs1) {
                    int ch2 = g_child_list[en + 1];
                    waitdone(&g_done[ch2]);
                    const float* hr2 = g_h + ch2 * 256;
#pragma unroll
                    for (int q = 0; q < 8; q++) hrB[q] = __ldcg(hr2 + q * 32 + lane);
                    cBpre = __ldcg(g_c + ch2 * 256 + col);
                }
            }
            if (pair) {
                // joint f-dot: one Wf stream feeds BOTH children
                u64 fa0 = 0, fa1 = 0, fb0 = 0, fb1 = 0;
#pragma unroll 8
                for (int k2 = 0; k2 < 128; k2 += 2) {
                    u64 w0 = Wf2[(k2 + 0) * 32 + lane];
                    u64 w1 = Wf2[(k2 + 1) * 32 + lane];
                    fma2(fa0, *(const u64*)(hA + 2 * k2),     w0);
                    fma2(fa1, *(const u64*)(hA + 2 * k2 + 2), w1);
                    fma2(fb0, *(const u64*)(hB + 2 * k2),     w0);
                    fma2(fb1, *(const u64*)(hB + 2 * k2 + 2), w1);
                }
                float f0 = sigm(red2(fa0) + red2(fa1) + bfh + fxn);
                float f1 = sigm(red2(fb0) + red2(fb1) + bfh + fxn);
                fc = fmaf(f0, cA, fmaf(f1, cB, fc));
            } else {
                u64 a0 = 0, a1 = 0, a2 = 0, a3 = 0;
#pragma unroll 8
                for (int k2 = 0; k2 < 128; k2 += 4) {
                    fma2(a0, *(const u64*)(hA + 2 * k2),     Wf2[(k2 + 0) * 32 + lane]);
                    fma2(a1, *(const u64*)(hA + 2 * k2 + 2), Wf2[(k2 + 1) * 32 + lane]);
                    fma2(a2, *(const u64*)(hA + 2 * k2 + 4), Wf2[(k2 + 2) * 32 + lane]);
                    fma2(a3, *(const u64*)(hA + 2 * k2 + 6), Wf2[(k2 + 3) * 32 + lane]);
                }
                float fd = red2(a0) + red2(a1) + red2(a2) + red2(a3);
                float f = sigm(fd + bfh + fxn);
                fc = fmaf(f, cA, fc);
            }
            __syncwarp();
        }

        // h_sum -> smem (broadcast source for i/o/u dots)
#pragma unroll
        for (int q = 0; q < 8; q++) hA[q * 32 + lane] = rs[q];
        __syncwarp();
        u64 i0 = 0, i1 = 0, o0 = 0, o1 = 0, u0 = 0, u1 = 0;
#pragma unroll 4
        for (int k2 = 0; k2 < 128; k2 += 2) {
            u64 p01 = *(const u64*)(hA + 2 * k2);
            u64 p23 = *(const u64*)(hA + 2 * k2 + 2);
            fma2(i0, p01, Wi2[(k2 + 0) * 32 + lane]);
            fma2(i1, p23, Wi2[(k2 + 1) * 32 + lane]);
            fma2(o0, p01, Wo2[(k2 + 0) * 32 + lane]);
            fma2(o1, p23, Wo2[(k2 + 1) * 32 + lane]);
            fma2(u0, p01, Wu2[(k2 + 0) * 32 + lane]);
            fma2(u1, p23, Wu2[(k2 + 1) * 32 + lane]);
        }
        float iv = sigm(ixv + red2(i0) + red2(i1) + bih);
        float ov = sigm(oxv + red2(o0) + red2(o1));
        float uv = tanhf(uxv + red2(u0) + red2(u1));
        float cn = fmaf(iv, uv, fc);
        __syncwarp();

        __stcg(g_c + n * 256 + col, cn);
        __stcg(g_h + n * 256 + col, ov * tanhf(cn));
        __syncwarp();
        if (lane == 0) red_release(&g_done[n]);
    }
}

// ---------------- parallel 2-stage max-pool + output ------------------------
__global__ void __launch_bounds__(256) pool1_kernel()
{
    int b = blockIdx.x, chn = blockIdx.y, t = threadIdx.x;
    const float* hb = g_h + ((size_t)b * St + chn * 16) * Hh;
    float m = -1e30f;
#pragma unroll
    for (int s2 = 0; s2 < 16; s2++) m = fmaxf(m, hb[s2 * Hh + t]);
    g_pool[(b * 8 + chn) * Hh + t] = m;
}

__global__ void __launch_bounds__(256) pool2_kernel(
    const float* __restrict__ Wout, const float* __restrict__ bout,
    float* __restrict__ out)
{
    __shared__ float pooled[Hh];
    int b = blockIdx.x, t = threadIdx.x;
    float m = -1e30f;
#pragma unroll
    for (int chn = 0; chn < 8; chn++)
        m = fmaxf(m, g_pool[(b * 8 + chn) * Hh + t]);
    pooled[t] = m;
    __syncthreads();
    if (t < Lc) {
        float acc = bout[t];
        for (int k = 0; k < Hh; k++) acc = fmaf(pooled[k], Wout[k * Lc + t], acc);
        out[b * Lc + t] = acc;
    }
}

// ---------------- host-side launch ------------------------------------------
extern "C" void kernel_launch(void* const* d_in, const int* in_sizes, int n_in,
                              void* d_out, int out_size)
{
    int off = (in_sizes[5] == 1) ? 6 : 5;

    const int* xs        = (const int*)d_in[0];
    const int* rels      = (const int*)d_in[1];
    const int* child_idx = (const int*)d_in[2];
    const int* parent_idx= (const int*)d_in[3];
    const int* height    = (const int*)d_in[4];
    const float* embW  = (const float*)d_in[off + 0];
    const float* relW  = (const float*)d_in[off + 1];
    const float* W_ix  = (const float*)d_in[off + 2];
    const float* b_ix  = (const float*)d_in[off + 3];
    const float* W_ih  = (const float*)d_in[off + 4];
    const float* b_ih  = (const float*)d_in[off + 5];
    const float* W_fx  = (const float*)d_in[off + 6];
    const float* b_fx  = (const float*)d_in[off + 7];
    const float* W_fh  = (const float*)d_in[off + 8];
    const float* b_fh  = (const float*)d_in[off + 9];
    const float* W_ox  = (const float*)d_in[off + 10];
    const float* W_oh  = (const float*)d_in[off + 11];
    const float* W_ux  = (const float*)d_in[off + 12];
    const float* W_uh  = (const float*)d_in[off + 13];
    const float* W_out = (const float*)d_in[off + 14];
    const float* b_out = (const float*)d_in[off + 15];

    cudaFuncSetAttribute(rec_kernel,
                         cudaFuncAttributeMaxDynamicSharedMemorySize, 163840);

    preprocess_kernel<<<1, 512>>>(child_idx, parent_idx, height);
    dim3 gg(4, 32, 4);
    input_gemm_kernel<<<gg, 256>>>(xs, rels, embW, relW,
                                   W_ix, W_fx, W_ox, W_ux, b_ix, b_fx);
    rec_kernel<<<NCTA, NTH, 163840>>>(W_ih, W_oh, W_uh, W_fh, b_ih, b_fh);
    pool1_kernel<<<dim3(16, 8), 256>>>();
    pool2_kernel<<<Bt, 256>>>(W_out, b_out, (float*)d_out);
}